// round 7
// baseline (speedup 1.0000x reference)
#include <cuda_runtime.h>
#include <math.h>

#define E 128
#define H 8
#define CTXLEN 257
#define THREADS 256
#define TANH_CLIP 10.0f

#define MAXB 1024
#define MAXNC 16          // chunks of 64 nodes, supports N <= 1024
#define CHUNK 64
#define LCHUNK 256        // logits nodes per block (8 warps x 32)

// ---------------- device scratch ----------------
__device__ float g_ctx[MAXB * 260];              // [mean(128) | cur(128) | rc | pad]
__device__ float g_qk[MAXB * H * E];
__device__ float g_wemb[MAXB * H * E];
__device__ float g_qk2[MAXB * E];
__device__ float g_pm[MAXB * MAXNC * H];
__device__ float g_pl[MAXB * MAXNC * H];
__device__ float g_pw[MAXB * MAXNC * H * E];
__device__ float g_sumexp[MAXB];
__device__ float g_P[E * E];                     // P = Wog @ Wqo
__device__ float g_M3[E * E];                    // M3[f][e] = sum_j Wko[f][j] P[e][j]
__device__ float g_T[H * E * E];                 // Tt[k][f], k = h*128+f'

__device__ __forceinline__ float warp_max(float v) {
    #pragma unroll
    for (int o = 16; o; o >>= 1) v = fmaxf(v, __shfl_xor_sync(0xffffffffu, v, o));
    return v;
}
__device__ __forceinline__ float warp_sum(float v) {
    #pragma unroll
    for (int o = 16; o; o >>= 1) v += __shfl_xor_sync(0xffffffffu, v, o);
    return v;
}

// ---------------- precompute composites ----------------
__global__ __launch_bounds__(128) void k_pre1(const float* __restrict__ Wog,
                                              const float* __restrict__ Wqo) {
    __shared__ float row[E];
    const int i = blockIdx.x, j = threadIdx.x;
    row[j] = Wog[i * E + j];
    __syncthreads();
    float acc = 0.f;
    #pragma unroll 8
    for (int k = 0; k < E; k++) acc = fmaf(row[k], Wqo[k * E + j], acc);
    g_P[i * E + j] = acc;
}

__global__ __launch_bounds__(128) void k_pre2(const float* __restrict__ Wko) {
    __shared__ float row[E];
    const int f = blockIdx.x, e = threadIdx.x;
    row[e] = Wko[f * E + e];
    __syncthreads();
    float acc = 0.f;
    #pragma unroll 8
    for (int j = 0; j < E; j++) acc = fmaf(row[j], g_P[e * E + j], acc);
    g_M3[f * E + e] = acc;
}

__global__ __launch_bounds__(THREADS) void k_pre3(const float* __restrict__ Wvg) {
    __shared__ float m3s[E * 16];
    __shared__ float wvs[E * 16];
    const int h = blockIdx.x, t = threadIdx.x;
    for (int idx = t; idx < E * 16; idx += THREADS) {
        int r = idx >> 4, d = idx & 15;
        m3s[idx] = g_M3[r * E + h * 16 + d];
        wvs[idx] = Wvg[r * E + h * 16 + d];
    }
    __syncthreads();
    const int fp = t & 127, fh = t >> 7;
    float wv[16];
    #pragma unroll
    for (int d = 0; d < 16; d++) wv[d] = wvs[fp * 16 + d];
    for (int f = fh * 64; f < fh * 64 + 64; f++) {
        float acc = 0.f;
        #pragma unroll
        for (int d = 0; d < 16; d++) acc = fmaf(m3s[f * 16 + d], wv[d], acc);
        g_T[(h * E + fp) * E + f] = acc;
    }
}

// ---------------- K1: graph mean + context build ----------------
__global__ __launch_bounds__(THREADS) void k_mean(
    const float* __restrict__ emb, const float* __restrict__ rc,
    const int* __restrict__ cur, int N)
{
    const int b = blockIdx.x, t = threadIdx.x, lane = t & 31, warp = t >> 5;
    __shared__ float4 red[THREADS];
    const float* embB = emb + (size_t)b * N * E;
    float4 acc = make_float4(0.f, 0.f, 0.f, 0.f);
    #pragma unroll 4
    for (int n = warp; n < N; n += 8) {
        float4 v = *(const float4*)(embB + (size_t)n * E + lane * 4);
        acc.x += v.x; acc.y += v.y; acc.z += v.z; acc.w += v.w;
    }
    red[t] = acc;
    __syncthreads();
    if (warp == 0) {
        float4 s = red[lane];
        #pragma unroll
        for (int r = 1; r < 8; r++) {
            float4 v = red[r * 32 + lane];
            s.x += v.x; s.y += v.y; s.z += v.z; s.w += v.w;
        }
        float invN = 1.0f / (float)N;
        float* d = g_ctx + b * 260 + lane * 4;
        d[0] = s.x * invN; d[1] = s.y * invN; d[2] = s.z * invN; d[3] = s.w * invN;
    } else if (warp == 1) {
        int cn = cur[b];
        float4 v = *(const float4*)(embB + (size_t)cn * E + lane * 4);
        float* d = g_ctx + b * 260 + 128 + lane * 4;
        d[0] = v.x; d[1] = v.y; d[2] = v.z; d[3] = v.w;
    }
    if (t == 64) { g_ctx[b * 260 + 256] = rc[b]; g_sumexp[b] = 0.f; }
}

// ---------------- K2: q = ctx@Wqg, qk = fold(Wkg, q) ----------------
// dyn smem: WKG[128*129]=16512 | CTX[260] | SQ[256] | Q[128] -> 17156 floats
#define K2_WKG 0
#define K2_CTX 16512
#define K2_SQ  (K2_CTX + 260)
#define K2_Q   (K2_SQ + 256)
#define K2_FLOATS (K2_Q + 128)
__global__ __launch_bounds__(THREADS) void k_ctx(
    const float* __restrict__ Wqg, const float* __restrict__ Wkg)
{
    extern __shared__ float sm[];
    const int b = blockIdx.x, t = threadIdx.x;

    for (int idx = t; idx < E * E; idx += THREADS)
        sm[K2_WKG + (idx >> 7) * 129 + (idx & 127)] = Wkg[idx];
    sm[K2_CTX + t] = g_ctx[b * 260 + t];
    if (t == 0) sm[K2_CTX + 256] = g_ctx[b * 260 + 256];
    __syncthreads();

    // phase A: q, split c-range across two half-blocks
    {
        const int j = t & 127, half = t >> 7;
        const int c0 = half ? 128 : 0;
        const int c1 = half ? CTXLEN : 128;
        float acc = 0.f;
        #pragma unroll 4
        for (int c = c0; c < c1; c++)
            acc = fmaf(sm[K2_CTX + c], Wqg[c * E + j], acc);
        sm[K2_SQ + half * 128 + j] = acc;
    }
    __syncthreads();
    if (t < 128) sm[K2_Q + t] = sm[K2_SQ + t] + sm[K2_SQ + 128 + t];
    __syncthreads();

    // phase B: qk[h][f] = sum_d q[h*16+d] * Wkg[f][h*16+d]
    #pragma unroll
    for (int k = 0; k < 4; k++) {
        int o = k * THREADS + t;
        int h = o >> 7, f = o & 127;
        float acc = 0.f;
        #pragma unroll
        for (int d = 0; d < 16; d++)
            acc = fmaf(sm[K2_Q + h * 16 + d], sm[K2_WKG + f * 129 + h * 16 + d], acc);
        g_qk[b * (H * E) + h * E + f] = acc;
    }
}

// ---------------- K3: split-K flash partials ----------------
__global__ __launch_bounds__(THREADS) void k_flash(
    const float* __restrict__ emb, const unsigned char* __restrict__ mask, int N)
{
    __shared__ float s_tile[CHUNK * 132];   // 8448 f
    __shared__ float s_qk[H * 132];         // 1056 f, reused as s_w [h*132+f]
    __shared__ float s_c[H * 68];           // padded: stride 68
    __shared__ float s_p[H * 68];
    __shared__ unsigned char s_m[CHUNK];

    const int c = blockIdx.x, b = blockIdx.y;
    const int t = threadIdx.x, lane = t & 31, warp = t >> 5;
    const int n0 = c * CHUNK;
    const int cnt = min(CHUNK, N - n0);

    for (int idx = t; idx < H * E; idx += THREADS)
        s_qk[(idx >> 7) * 132 + (idx & 127)] = g_qk[b * (H * E) + idx];
    if (t < CHUNK)
        s_m[t] = (t < cnt) ? mask[(size_t)b * N + n0 + t] : (unsigned char)1;

    const float* embB = emb + ((size_t)b * N + n0) * E;
    for (int j = t; j < cnt * 32; j += THREADS) {
        int i = j >> 5, c4 = j & 31;
        *(float4*)(s_tile + i * 132 + c4 * 4) =
            *(const float4*)(embB + (size_t)i * E + c4 * 4);
    }
    __syncthreads();

    // compat: thread = (i0 = t>>3 node group, h = t&7); nodes i0 and i0+32
    // 4 accumulator chains (2 per node) to halve FMA dependency latency
    {
        const int h = t & 7, i0 = t >> 3;
        const float4* qk4 = (const float4*)(s_qk + h * 132);
        const float4* e0  = (const float4*)(s_tile + i0 * 132);
        const float4* e1  = (const float4*)(s_tile + (i0 + 32) * 132);
        float a0 = 0.f, a1 = 0.f, b0 = 0.f, b1 = 0.f;
        #pragma unroll 8
        for (int f4 = 0; f4 < 32; f4 += 2) {
            float4 q = qk4[f4];
            float4 x = e0[f4];
            float4 y = e1[f4];
            a0 = fmaf(q.x, x.x, a0); a1 = fmaf(q.x, y.x, a1);
            a0 = fmaf(q.y, x.y, a0); a1 = fmaf(q.y, y.y, a1);
            a0 = fmaf(q.z, x.z, a0); a1 = fmaf(q.z, y.z, a1);
            a0 = fmaf(q.w, x.w, a0); a1 = fmaf(q.w, y.w, a1);
            float4 q2 = qk4[f4 + 1];
            float4 x2 = e0[f4 + 1];
            float4 y2 = e1[f4 + 1];
            b0 = fmaf(q2.x, x2.x, b0); b1 = fmaf(q2.x, y2.x, b1);
            b0 = fmaf(q2.y, x2.y, b0); b1 = fmaf(q2.y, y2.y, b1);
            b0 = fmaf(q2.z, x2.z, b0); b1 = fmaf(q2.z, y2.z, b1);
            b0 = fmaf(q2.w, x2.w, b0); b1 = fmaf(q2.w, y2.w, b1);
        }
        float r0 = a0 + b0, r1 = a1 + b1;
        s_c[h * 68 + i0]      = s_m[i0]      ? -1e30f : r0 * 0.25f;
        s_c[h * 68 + i0 + 32] = s_m[i0 + 32] ? -1e30f : r1 * 0.25f;
    }
    __syncthreads();

    // per-head local softmax partial (warp == head)
    {
        const int h = warp;
        float c0 = s_c[h * 68 + lane];
        float c1 = s_c[h * 68 + lane + 32];
        float m = warp_max(fmaxf(c0, c1));
        float p0 = __expf(c0 - m);
        float p1 = __expf(c1 - m);
        if (lane >= cnt)      p0 = 0.f;
        if (lane + 32 >= cnt) p1 = 0.f;
        s_p[h * 68 + lane]      = p0;
        s_p[h * 68 + lane + 32] = p1;
        float l = warp_sum(p0 + p1);
        const int base = (b * MAXNC + c) * H + h;
        if (lane == 0) { g_pm[base] = m; g_pl[base] = l; }
    }
    __syncthreads();

    // wemb: thread = (fg = t>>3 feat group, h = t&7); result into s_w (= s_qk)
    {
        const int h = t & 7, fg = t >> 3;
        float wx = 0.f, wy = 0.f, wz = 0.f, ww = 0.f;
        #pragma unroll 4
        for (int i = 0; i < cnt; i++) {
            float pv = s_p[h * 68 + i];
            float4 e4 = *(const float4*)(s_tile + i * 132 + fg * 4);
            wx = fmaf(pv, e4.x, wx);
            wy = fmaf(pv, e4.y, wy);
            wz = fmaf(pv, e4.z, wz);
            ww = fmaf(pv, e4.w, ww);
        }
        *(float4*)(s_qk + h * 132 + fg * 4) = make_float4(wx, wy, wz, ww);
    }
    __syncthreads();

    float* dst = g_pw + (size_t)(b * MAXNC + c) * (H * E);
    for (int idx = t; idx < H * E; idx += THREADS)
        dst[idx] = s_qk[(idx >> 7) * 132 + (idx & 127)];
}

// ---------------- K4a: combine partials -> normalized wemb ----------------
__global__ __launch_bounds__(THREADS) void k_norm(int nchunk) {
    const int b = blockIdx.x, t = threadIdx.x, lane = t & 31, h = t >> 5;
    float m = -1e30f;
    for (int c = 0; c < nchunk; c++)
        m = fmaxf(m, g_pm[(b * MAXNC + c) * H + h]);
    float L = 0.f;
    float4 w = make_float4(0.f, 0.f, 0.f, 0.f);
    for (int c = 0; c < nchunk; c++) {
        const int base = (b * MAXNC + c) * H + h;
        float s = __expf(g_pm[base] - m);
        L = fmaf(s, g_pl[base], L);
        float4 pw = *(const float4*)(g_pw + (size_t)(b * MAXNC + c) * (H * E) + h * E + lane * 4);
        w.x = fmaf(s, pw.x, w.x); w.y = fmaf(s, pw.y, w.y);
        w.z = fmaf(s, pw.z, w.z); w.w = fmaf(s, pw.w, w.w);
    }
    float invL = 1.0f / L;
    float* d = g_wemb + b * (H * E) + h * E + lane * 4;
    d[0] = w.x * invL; d[1] = w.y * invL; d[2] = w.z * invL; d[3] = w.w * invL;
}

// ---------------- K4b: qk2 = wemb @ Tt (aligned, conflict-aware) ----------------
// smem: sg[8192] wemb as [k][8] (32B-aligned per k) | red[2048] -> 10240 floats
__global__ __launch_bounds__(THREADS) void k_gemm(int B) {
    extern __shared__ float sg[];
    float* red = sg + 8192;
    const int b0 = blockIdx.x * 8, t = threadIdx.x;

    for (int idx = t; idx < 8192; idx += THREADS) {
        int bb = idx >> 10, k = idx & 1023;
        sg[k * 8 + bb] = g_wemb[(size_t)(b0 + bb) * (H * E) + k];
    }
    __syncthreads();

    const int f = t & 127, half = t >> 7;
    float acc[8];
    #pragma unroll
    for (int i = 0; i < 8; i++) acc[i] = 0.f;

    const int k0 = half * 512;
    #pragma unroll 4
    for (int k = k0; k < k0 + 512; k++) {
        float tv = g_T[(size_t)k * E + f];          // coalesced, L2-resident
        float wq[8];
        *(float4*)(wq)     = *(const float4*)(sg + k * 8);      // broadcast
        *(float4*)(wq + 4) = *(const float4*)(sg + k * 8 + 4);  // broadcast
        #pragma unroll
        for (int bb = 0; bb < 8; bb++)
            acc[bb] = fmaf(tv, wq[bb], acc[bb]);
    }

    #pragma unroll
    for (int bb = 0; bb < 8; bb++)
        red[half * 1024 + bb * 128 + f] = acc[bb];  // f in low bits: conflict-free
    __syncthreads();

    #pragma unroll
    for (int j = 0; j < 4; j++) {
        int o = t + j * 256;
        int bb = o >> 7, ff = o & 127;
        float s = red[o] + red[1024 + o];
        if (b0 + bb < B) g_qk2[(size_t)(b0 + bb) * E + ff] = s;
    }
}

// ---------------- K5: logits + sumexp (4-lane cooperative dots) ----------------
__global__ __launch_bounds__(THREADS) void k_logits(
    const float* __restrict__ emb, const unsigned char* __restrict__ mask,
    float* __restrict__ out, int N, int B)
{
    const int cblk = blockIdx.x, b = blockIdx.y;
    const int t = threadIdx.x, lane = t & 31, warp = t >> 5;
    const int q = lane & 3;          // feature quarter
    const int ns = lane >> 2;        // node sub-index within group of 8
    const int n_base = cblk * LCHUNK + warp * 32;

    __shared__ float s_lg[LCHUNK];
    __shared__ float s_sum[8];

    // qk2 quarter cached in registers: feats q*32 .. q*32+31
    float4 qreg[8];
    #pragma unroll
    for (int j = 0; j < 8; j++)
        qreg[j] = *(const float4*)(g_qk2 + b * E + q * 32 + j * 4);

    const float inv_sqrtE = 0.08838834764831845f;  // 1/sqrt(128)
    const size_t BN = (size_t)B * N;
    const float* embB = emb + (size_t)b * N * E;

    float lsum = 0.f;
    #pragma unroll
    for (int g = 0; g < 4; g++) {
        const int n = n_base + g * 8 + ns;
        float acc = 0.f;
        if (n < N) {
            const float4* ep = (const float4*)(embB + (size_t)n * E + q * 32);
            #pragma unroll
            for (int j = 0; j < 8; j++) {
                float4 e4 = ep[j];
                acc = fmaf(e4.x, qreg[j].x, acc);
                acc = fmaf(e4.y, qreg[j].y, acc);
                acc = fmaf(e4.z, qreg[j].z, acc);
                acc = fmaf(e4.w, qreg[j].w, acc);
            }
        }
        acc += __shfl_xor_sync(0xffffffffu, acc, 1);
        acc += __shfl_xor_sync(0xffffffffu, acc, 2);
        if (q == 0 && n < N) {
            float x = acc * inv_sqrtE;
            x = fminf(fmaxf(x, -15.f), 15.f);
            float ex = __expf(2.f * x);
            float lg = TANH_CLIP * (ex - 1.f) / (ex + 1.f);
            if (mask[(size_t)b * N + n]) lg = -INFINITY;
            s_lg[warp * 32 + g * 8 + ns] = lg;
            lsum += __expf(lg - TANH_CLIP);
        }
    }
    lsum = warp_sum(lsum);
    if (lane == 0) s_sum[warp] = lsum;
    __syncthreads();
    if (t == 0) {
        float s = 0.f;
        #pragma unroll
        for (int w = 0; w < 8; w++) s += s_sum[w];
        atomicAdd(&g_sumexp[b], s);
    }
    {
        const int n = cblk * LCHUNK + t;
        if (n < N) out[BN + (size_t)b * N + n] = s_lg[t];
    }
}

// ---------------- K6: probs ----------------
__global__ __launch_bounds__(THREADS) void k_probs(float* __restrict__ out, int N, int B) {
    const int b = blockIdx.x, t = threadIdx.x;
    const size_t BN = (size_t)B * N;
    float inv = 1.0f / g_sumexp[b];
    for (int n = t; n < N; n += THREADS) {
        float lg = out[BN + (size_t)b * N + n];
        out[(size_t)b * N + n] = __expf(lg - TANH_CLIP) * inv;
    }
}

// ---------------- launch ----------------
extern "C" void kernel_launch(void* const* d_in, const int* in_sizes, int n_in,
                              void* d_out, int out_size) {
    const float* emb = (const float*)d_in[0];
    const float* rc  = (const float*)d_in[1];
    const float* Wqg = (const float*)d_in[2];
    const float* Wkg = (const float*)d_in[3];
    const float* Wvg = (const float*)d_in[4];
    const float* Wog = (const float*)d_in[5];
    const float* Wqo = (const float*)d_in[6];
    const float* Wko = (const float*)d_in[7];
    const int*   cur = (const int*)d_in[8];
    const unsigned char* mask = (const unsigned char*)d_in[9];

    int B = in_sizes[1];
    int N = in_sizes[0] / (B * E);
    float* out = (float*)d_out;

    int nchunk  = (N + CHUNK - 1) / CHUNK;
    int nlchunk = (N + LCHUNK - 1) / LCHUNK;
    int ngemm   = (B + 7) / 8;

    static bool attr_done = false;
    if (!attr_done) {
        cudaFuncSetAttribute(k_ctx,  cudaFuncAttributeMaxDynamicSharedMemorySize,
                             K2_FLOATS * (int)sizeof(float));
        cudaFuncSetAttribute(k_gemm, cudaFuncAttributeMaxDynamicSharedMemorySize,
                             10240 * (int)sizeof(float));
        attr_done = true;
    }

    k_pre1<<<E, 128>>>(Wog, Wqo);
    k_pre2<<<E, 128>>>(Wko);
    k_pre3<<<H, THREADS>>>(Wvg);
    k_mean<<<B, THREADS>>>(emb, rc, cur, N);
    k_ctx<<<B, THREADS, K2_FLOATS * sizeof(float)>>>(Wqg, Wkg);
    k_flash<<<dim3(nchunk, B), THREADS>>>(emb, mask, N);
    k_norm<<<B, THREADS>>>(nchunk);
    k_gemm<<<ngemm, THREADS, 10240 * sizeof(float)>>>(B);
    k_logits<<<dim3(nlchunk, B), THREADS>>>(emb, mask, out, N, B);
    k_probs<<<B, THREADS>>>(out, N, B);
}

// round 8
// speedup vs baseline: 1.1094x; 1.1094x over previous
#include <cuda_runtime.h>
#include <math.h>

#define E 128
#define H 8
#define CTXLEN 257
#define THREADS 256
#define TANH_CLIP 10.0f

#define MAXB 1024
#define MAXNC 16          // chunks of 64 nodes, supports N <= 1024
#define CHUNK 64
#define LCHUNK 256        // logits nodes per block

// ---------------- device scratch ----------------
__device__ float g_ctx[MAXB * 260];              // [mean(128) | cur(128) | rc | pad]
__device__ float g_qk[MAXB * H * E];
__device__ float g_wemb[MAXB * H * E];
__device__ float g_qk2[MAXB * E];
__device__ float g_pm[MAXB * MAXNC * H];
__device__ float g_pl[MAXB * MAXNC * H];
__device__ float g_pw[MAXB * MAXNC * H * E];
__device__ float g_sumexp[MAXB];
__device__ float g_P[E * E];                     // P = Wog @ Wqo
__device__ float g_M3[E * E];                    // M3[f][e] = sum_j Wko[f][j] P[e][j]
__device__ float g_T[H * E * E];                 // Tt[k][f], k = h*128+f'

__device__ __forceinline__ float warp_max(float v) {
    #pragma unroll
    for (int o = 16; o; o >>= 1) v = fmaxf(v, __shfl_xor_sync(0xffffffffu, v, o));
    return v;
}
__device__ __forceinline__ float warp_sum(float v) {
    #pragma unroll
    for (int o = 16; o; o >>= 1) v += __shfl_xor_sync(0xffffffffu, v, o);
    return v;
}

// ---------------- precompute composites ----------------
__global__ __launch_bounds__(128) void k_pre1(const float* __restrict__ Wog,
                                              const float* __restrict__ Wqo) {
    __shared__ float row[E];
    const int i = blockIdx.x, j = threadIdx.x;
    row[j] = Wog[i * E + j];
    __syncthreads();
    float acc = 0.f;
    #pragma unroll 8
    for (int k = 0; k < E; k++) acc = fmaf(row[k], Wqo[k * E + j], acc);
    g_P[i * E + j] = acc;
}

__global__ __launch_bounds__(128) void k_pre2(const float* __restrict__ Wko) {
    __shared__ float row[E];
    const int f = blockIdx.x, e = threadIdx.x;
    row[e] = Wko[f * E + e];
    __syncthreads();
    float acc = 0.f;
    #pragma unroll 8
    for (int j = 0; j < E; j++) acc = fmaf(row[j], g_P[e * E + j], acc);
    g_M3[f * E + e] = acc;
}

__global__ __launch_bounds__(THREADS) void k_pre3(const float* __restrict__ Wvg) {
    __shared__ float m3s[E * 16];
    __shared__ float wvs[E * 16];
    const int h = blockIdx.x, t = threadIdx.x;
    for (int idx = t; idx < E * 16; idx += THREADS) {
        int r = idx >> 4, d = idx & 15;
        m3s[idx] = g_M3[r * E + h * 16 + d];
        wvs[idx] = Wvg[r * E + h * 16 + d];
    }
    __syncthreads();
    const int fp = t & 127, fh = t >> 7;
    float wv[16];
    #pragma unroll
    for (int d = 0; d < 16; d++) wv[d] = wvs[fp * 16 + d];
    for (int f = fh * 64; f < fh * 64 + 64; f++) {
        float acc = 0.f;
        #pragma unroll
        for (int d = 0; d < 16; d++) acc = fmaf(m3s[f * 16 + d], wv[d], acc);
        g_T[(h * E + fp) * E + f] = acc;
    }
}

// ---------------- K1: graph mean + context build ----------------
__global__ __launch_bounds__(THREADS) void k_mean(
    const float* __restrict__ emb, const float* __restrict__ rc,
    const int* __restrict__ cur, int N)
{
    const int b = blockIdx.x, t = threadIdx.x, lane = t & 31, warp = t >> 5;
    __shared__ float4 red[THREADS];
    const float* embB = emb + (size_t)b * N * E;
    float4 acc = make_float4(0.f, 0.f, 0.f, 0.f);
    #pragma unroll 4
    for (int n = warp; n < N; n += 8) {
        float4 v = *(const float4*)(embB + (size_t)n * E + lane * 4);
        acc.x += v.x; acc.y += v.y; acc.z += v.z; acc.w += v.w;
    }
    red[t] = acc;
    __syncthreads();
    if (warp == 0) {
        float4 s = red[lane];
        #pragma unroll
        for (int r = 1; r < 8; r++) {
            float4 v = red[r * 32 + lane];
            s.x += v.x; s.y += v.y; s.z += v.z; s.w += v.w;
        }
        float invN = 1.0f / (float)N;
        float* d = g_ctx + b * 260 + lane * 4;
        d[0] = s.x * invN; d[1] = s.y * invN; d[2] = s.z * invN; d[3] = s.w * invN;
    } else if (warp == 1) {
        int cn = cur[b];
        float4 v = *(const float4*)(embB + (size_t)cn * E + lane * 4);
        float* d = g_ctx + b * 260 + 128 + lane * 4;
        d[0] = v.x; d[1] = v.y; d[2] = v.z; d[3] = v.w;
    }
    if (t == 64) { g_ctx[b * 260 + 256] = rc[b]; g_sumexp[b] = 0.f; }
}

// ---------------- K2: q = ctx@Wqg, qk = fold(Wkg, q) ----------------
// dyn smem: WKG[128*129]=16512 | CTX[260] | SQ[256] | Q[128] -> 17156 floats
#define K2_WKG 0
#define K2_CTX 16512
#define K2_SQ  (K2_CTX + 260)
#define K2_Q   (K2_SQ + 256)
#define K2_FLOATS (K2_Q + 128)
__global__ __launch_bounds__(THREADS) void k_ctx(
    const float* __restrict__ Wqg, const float* __restrict__ Wkg)
{
    extern __shared__ float sm[];
    const int b = blockIdx.x, t = threadIdx.x;

    for (int idx = t; idx < E * E; idx += THREADS)
        sm[K2_WKG + (idx >> 7) * 129 + (idx & 127)] = Wkg[idx];
    sm[K2_CTX + t] = g_ctx[b * 260 + t];
    if (t == 0) sm[K2_CTX + 256] = g_ctx[b * 260 + 256];
    __syncthreads();

    // phase A: q, split c-range across two half-blocks
    {
        const int j = t & 127, half = t >> 7;
        const int c0 = half ? 128 : 0;
        const int c1 = half ? CTXLEN : 128;
        float acc = 0.f;
        #pragma unroll 4
        for (int c = c0; c < c1; c++)
            acc = fmaf(sm[K2_CTX + c], Wqg[c * E + j], acc);
        sm[K2_SQ + half * 128 + j] = acc;
    }
    __syncthreads();
    if (t < 128) sm[K2_Q + t] = sm[K2_SQ + t] + sm[K2_SQ + 128 + t];
    __syncthreads();

    // phase B: qk[h][f] = sum_d q[h*16+d] * Wkg[f][h*16+d]
    #pragma unroll
    for (int k = 0; k < 4; k++) {
        int o = k * THREADS + t;
        int h = o >> 7, f = o & 127;
        float acc = 0.f;
        #pragma unroll
        for (int d = 0; d < 16; d++)
            acc = fmaf(sm[K2_Q + h * 16 + d], sm[K2_WKG + f * 129 + h * 16 + d], acc);
        g_qk[b * (H * E) + h * E + f] = acc;
    }
}

// ---------------- K3: split-K flash partials (R6 version) ----------------
__global__ __launch_bounds__(THREADS) void k_flash(
    const float* __restrict__ emb, const unsigned char* __restrict__ mask, int N)
{
    __shared__ float s_tile[CHUNK * 132];   // 8448 f
    __shared__ float s_qk[H * 132];         // 1056 f, reused as s_w [h*132+f]
    __shared__ float s_c[H * 68];           // padded: stride 68
    __shared__ float s_p[H * 68];
    __shared__ unsigned char s_m[CHUNK];

    const int c = blockIdx.x, b = blockIdx.y;
    const int t = threadIdx.x, lane = t & 31, warp = t >> 5;
    const int n0 = c * CHUNK;
    const int cnt = min(CHUNK, N - n0);

    for (int idx = t; idx < H * E; idx += THREADS)
        s_qk[(idx >> 7) * 132 + (idx & 127)] = g_qk[b * (H * E) + idx];
    if (t < CHUNK)
        s_m[t] = (t < cnt) ? mask[(size_t)b * N + n0 + t] : (unsigned char)1;

    const float* embB = emb + ((size_t)b * N + n0) * E;
    for (int j = t; j < cnt * 32; j += THREADS) {
        int i = j >> 5, c4 = j & 31;
        *(float4*)(s_tile + i * 132 + c4 * 4) =
            *(const float4*)(embB + (size_t)i * E + c4 * 4);
    }
    __syncthreads();

    // compat: thread = (i0 = t>>3 node group, h = t&7); nodes i0 and i0+32
    {
        const int h = t & 7, i0 = t >> 3;
        const float4* qk4 = (const float4*)(s_qk + h * 132);
        const float4* e0  = (const float4*)(s_tile + i0 * 132);
        const float4* e1  = (const float4*)(s_tile + (i0 + 32) * 132);
        float a0 = 0.f, a1 = 0.f;
        #pragma unroll 8
        for (int f4 = 0; f4 < 32; f4++) {
            float4 q = qk4[f4];
            float4 x = e0[f4];
            float4 y = e1[f4];
            a0 = fmaf(q.x, x.x, a0); a1 = fmaf(q.x, y.x, a1);
            a0 = fmaf(q.y, x.y, a0); a1 = fmaf(q.y, y.y, a1);
            a0 = fmaf(q.z, x.z, a0); a1 = fmaf(q.z, y.z, a1);
            a0 = fmaf(q.w, x.w, a0); a1 = fmaf(q.w, y.w, a1);
        }
        s_c[h * 68 + i0]      = s_m[i0]      ? -1e30f : a0 * 0.25f;
        s_c[h * 68 + i0 + 32] = s_m[i0 + 32] ? -1e30f : a1 * 0.25f;
    }
    __syncthreads();

    // per-head local softmax partial (warp == head)
    {
        const int h = warp;
        float c0 = s_c[h * 68 + lane];
        float c1 = s_c[h * 68 + lane + 32];
        float m = warp_max(fmaxf(c0, c1));
        float p0 = __expf(c0 - m);
        float p1 = __expf(c1 - m);
        if (lane >= cnt)      p0 = 0.f;
        if (lane + 32 >= cnt) p1 = 0.f;
        s_p[h * 68 + lane]      = p0;
        s_p[h * 68 + lane + 32] = p1;
        float l = warp_sum(p0 + p1);
        const int base = (b * MAXNC + c) * H + h;
        if (lane == 0) { g_pm[base] = m; g_pl[base] = l; }
    }
    __syncthreads();

    // wemb: thread = (fg = t>>3 feat group, h = t&7); result into s_w (= s_qk)
    {
        const int h = t & 7, fg = t >> 3;
        float wx = 0.f, wy = 0.f, wz = 0.f, ww = 0.f;
        #pragma unroll 4
        for (int i = 0; i < cnt; i++) {
            float pv = s_p[h * 68 + i];
            float4 e4 = *(const float4*)(s_tile + i * 132 + fg * 4);
            wx = fmaf(pv, e4.x, wx);
            wy = fmaf(pv, e4.y, wy);
            wz = fmaf(pv, e4.z, wz);
            ww = fmaf(pv, e4.w, ww);
        }
        *(float4*)(s_qk + h * 132 + fg * 4) = make_float4(wx, wy, wz, ww);
    }
    __syncthreads();

    float* dst = g_pw + (size_t)(b * MAXNC + c) * (H * E);
    for (int idx = t; idx < H * E; idx += THREADS)
        dst[idx] = s_qk[(idx >> 7) * 132 + (idx & 127)];
}

// ---------------- K4a: combine partials -> normalized wemb ----------------
__global__ __launch_bounds__(THREADS) void k_norm(int nchunk) {
    const int b = blockIdx.x, t = threadIdx.x, lane = t & 31, h = t >> 5;
    float m = -1e30f;
    for (int c = 0; c < nchunk; c++)
        m = fmaxf(m, g_pm[(b * MAXNC + c) * H + h]);
    float L = 0.f;
    float4 w = make_float4(0.f, 0.f, 0.f, 0.f);
    for (int c = 0; c < nchunk; c++) {
        const int base = (b * MAXNC + c) * H + h;
        float s = __expf(g_pm[base] - m);
        L = fmaf(s, g_pl[base], L);
        float4 pw = *(const float4*)(g_pw + (size_t)(b * MAXNC + c) * (H * E) + h * E + lane * 4);
        w.x = fmaf(s, pw.x, w.x); w.y = fmaf(s, pw.y, w.y);
        w.z = fmaf(s, pw.z, w.z); w.w = fmaf(s, pw.w, w.w);
    }
    float invL = 1.0f / L;
    float* d = g_wemb + b * (H * E) + h * E + lane * 4;
    d[0] = w.x * invL; d[1] = w.y * invL; d[2] = w.z * invL; d[3] = w.w * invL;
}

// ---------------- K4b: qk2 = wemb @ Tt (aligned, conflict-aware) ----------------
// smem: sg[8192] wemb as [k][8] (32B-aligned per k) | red[2048] -> 10240 floats
__global__ __launch_bounds__(THREADS) void k_gemm(int B) {
    extern __shared__ float sg[];
    float* red = sg + 8192;
    const int b0 = blockIdx.x * 8, t = threadIdx.x;

    for (int idx = t; idx < 8192; idx += THREADS) {
        int bb = idx >> 10, k = idx & 1023;
        sg[k * 8 + bb] = g_wemb[(size_t)(b0 + bb) * (H * E) + k];
    }
    __syncthreads();

    const int f = t & 127, half = t >> 7;
    float acc[8];
    #pragma unroll
    for (int i = 0; i < 8; i++) acc[i] = 0.f;

    const int k0 = half * 512;
    #pragma unroll 4
    for (int k = k0; k < k0 + 512; k++) {
        float tv = g_T[(size_t)k * E + f];          // coalesced, L2-resident
        float wq[8];
        *(float4*)(wq)     = *(const float4*)(sg + k * 8);      // broadcast
        *(float4*)(wq + 4) = *(const float4*)(sg + k * 8 + 4);  // broadcast
        #pragma unroll
        for (int bb = 0; bb < 8; bb++)
            acc[bb] = fmaf(tv, wq[bb], acc[bb]);
    }

    #pragma unroll
    for (int bb = 0; bb < 8; bb++)
        red[half * 1024 + bb * 128 + f] = acc[bb];  // f in low bits: conflict-free
    __syncthreads();

    #pragma unroll
    for (int j = 0; j < 4; j++) {
        int o = t + j * 256;
        int bb = o >> 7, ff = o & 127;
        float s = red[o] + red[1024 + o];
        if (b0 + bb < B) g_qk2[(size_t)(b0 + bb) * E + ff] = s;
    }
}

// ---------------- K5: logits + sumexp (two-phase smem reduce) ----------------
// Phase 1: warp per node-row (coalesced LDG.128, per-lane 4-feat partial -> smem)
// Phase 2: thread per node (serial 32 LDS, conflict-free), tanh/mask, coalesced out
__global__ __launch_bounds__(THREADS) void k_logits(
    const float* __restrict__ emb, const unsigned char* __restrict__ mask,
    float* __restrict__ out, int N, int B)
{
    const int cblk = blockIdx.x, b = blockIdx.y;
    const int t = threadIdx.x, lane = t & 31, warp = t >> 5;
    const int n0 = cblk * LCHUNK;

    __shared__ float s_part[LCHUNK * 33];   // padded
    __shared__ float s_sum[8];

    float4 qv = *(const float4*)(g_qk2 + b * E + lane * 4);
    const float* embB = emb + (size_t)b * N * E;
    const size_t BN = (size_t)B * N;

    // phase 1: warp w covers nodes n0 + w*32 + k, k = 0..31
    #pragma unroll 4
    for (int k = 0; k < 32; k++) {
        const int nl = warp * 32 + k;
        const int n = n0 + nl;
        float p = 0.f;
        if (n < N) {
            float4 e4 = *(const float4*)(embB + (size_t)n * E + lane * 4);
            p = e4.x * qv.x;
            p = fmaf(e4.y, qv.y, p);
            p = fmaf(e4.z, qv.z, p);
            p = fmaf(e4.w, qv.w, p);
        }
        s_part[nl * 33 + lane] = p;
    }
    __syncthreads();

    // phase 2: thread t handles node n0 + t
    const float inv_sqrtE = 0.08838834764831845f;  // 1/sqrt(128)
    float lsum = 0.f;
    {
        const int n = n0 + t;
        if (n < N) {
            float s0 = 0.f, s1 = 0.f, s2 = 0.f, s3 = 0.f;
            #pragma unroll
            for (int j = 0; j < 32; j += 4) {
                s0 += s_part[t * 33 + j];
                s1 += s_part[t * 33 + j + 1];
                s2 += s_part[t * 33 + j + 2];
                s3 += s_part[t * 33 + j + 3];
            }
            float d = (s0 + s1) + (s2 + s3);
            float x = d * inv_sqrtE;
            x = fminf(fmaxf(x, -15.f), 15.f);
            float ex = __expf(2.f * x);
            float lg = TANH_CLIP * (ex - 1.f) / (ex + 1.f);
            if (mask[(size_t)b * N + n]) lg = -INFINITY;
            out[BN + (size_t)b * N + n] = lg;
            lsum = __expf(lg - TANH_CLIP);
        }
    }
    lsum = warp_sum(lsum);
    if (lane == 0) s_sum[warp] = lsum;
    __syncthreads();
    if (t == 0) {
        float s = 0.f;
        #pragma unroll
        for (int w = 0; w < 8; w++) s += s_sum[w];
        atomicAdd(&g_sumexp[b], s);
    }
}

// ---------------- K6: probs ----------------
__global__ __launch_bounds__(THREADS) void k_probs(float* __restrict__ out, int N, int B) {
    const int b = blockIdx.x, t = threadIdx.x;
    const size_t BN = (size_t)B * N;
    float inv = 1.0f / g_sumexp[b];
    for (int n = t; n < N; n += THREADS) {
        float lg = out[BN + (size_t)b * N + n];
        out[(size_t)b * N + n] = __expf(lg - TANH_CLIP) * inv;
    }
}

// ---------------- launch ----------------
extern "C" void kernel_launch(void* const* d_in, const int* in_sizes, int n_in,
                              void* d_out, int out_size) {
    const float* emb = (const float*)d_in[0];
    const float* rc  = (const float*)d_in[1];
    const float* Wqg = (const float*)d_in[2];
    const float* Wkg = (const float*)d_in[3];
    const float* Wvg = (const float*)d_in[4];
    const float* Wog = (const float*)d_in[5];
    const float* Wqo = (const float*)d_in[6];
    const float* Wko = (const float*)d_in[7];
    const int*   cur = (const int*)d_in[8];
    const unsigned char* mask = (const unsigned char*)d_in[9];

    int B = in_sizes[1];
    int N = in_sizes[0] / (B * E);
    float* out = (float*)d_out;

    int nchunk  = (N + CHUNK - 1) / CHUNK;
    int nlchunk = (N + LCHUNK - 1) / LCHUNK;
    int ngemm   = (B + 7) / 8;

    static bool attr_done = false;
    if (!attr_done) {
        cudaFuncSetAttribute(k_ctx,  cudaFuncAttributeMaxDynamicSharedMemorySize,
                             K2_FLOATS * (int)sizeof(float));
        cudaFuncSetAttribute(k_gemm, cudaFuncAttributeMaxDynamicSharedMemorySize,
                             10240 * (int)sizeof(float));
        attr_done = true;
    }

    // Order chosen so k_flash is the 4th launch (ncu capture slot).
    // pre2/pre3 only feed k_gemm, so they may run after k_flash.
    k_pre1<<<E, 128>>>(Wog, Wqo);
    k_mean<<<B, THREADS>>>(emb, rc, cur, N);
    k_ctx<<<B, THREADS, K2_FLOATS * sizeof(float)>>>(Wqg, Wkg);
    k_flash<<<dim3(nchunk, B), THREADS>>>(emb, mask, N);
    k_pre2<<<E, 128>>>(Wko);
    k_pre3<<<H, THREADS>>>(Wvg);
    k_norm<<<B, THREADS>>>(nchunk);
    k_gemm<<<ngemm, THREADS, 10240 * sizeof(float)>>>(B);
    k_logits<<<dim3(nlchunk, B), THREADS>>>(emb, mask, out, N, B);
    k_probs<<<B, THREADS>>>(out, N, B);
}